// round 1
// baseline (speedup 1.0000x reference)
#include <cuda_runtime.h>
#include <cuda_bf16.h>
#include <cstdint>

// ---------------------------------------------------------------------------
// Problem constants
// ---------------------------------------------------------------------------
#define BATCH   512
#define NTOK    196          // 14*14 window
#define DIM     512
#define HEADS   8
#define HDIM    64           // DIM / HEADS
#define MROWS   (BATCH * NTOK)       // 100352
#define WIN     14
#define TBL     729          // (2*14-1)^2
#define SCALE_F 0.125f       // 64^-0.5

// ---------------------------------------------------------------------------
// Scratch (device globals: allocation-free contract)
// ---------------------------------------------------------------------------
__device__ float g_qkv [(size_t)MROWS * 3 * DIM];   // ~616 MB
__device__ float g_attn[(size_t)MROWS * DIM];       // ~205 MB
__device__ float g_bias[HEADS * NTOK * NTOK];       // ~1.2 MB

// ---------------------------------------------------------------------------
// Fast exp (avoid MUFU throughput wall in softmax): degree-6 exp2 polynomial
// ---------------------------------------------------------------------------
__device__ __forceinline__ float fast_exp(float x) {
    float t = x * 1.4426950408889634f;         // log2(e)
    t = fmaxf(t, -126.0f);
    float fi = floorf(t);
    float f  = t - fi;
    // 2^f on [0,1): Taylor in ln2, trunc err ~2e-5
    float p = 1.5413220e-4f;
    p = fmaf(p, f, 1.3333558e-3f);
    p = fmaf(p, f, 9.6181291e-3f);
    p = fmaf(p, f, 5.5504109e-2f);
    p = fmaf(p, f, 2.4022651e-1f);
    p = fmaf(p, f, 6.9314718e-1f);
    p = fmaf(p, f, 1.0f);
    int ei = (int)fi;
    float sc = __int_as_float((unsigned)(ei + 127) << 23);
    return p * sc;
}

// ---------------------------------------------------------------------------
// Kernel: gather relative-position bias -> g_bias[h][i][j]
// ---------------------------------------------------------------------------
__global__ void bias_gather_kernel(const float* __restrict__ table) {
    int idx = blockIdx.x * blockDim.x + threadIdx.x;
    if (idx >= NTOK * NTOK) return;
    int i = idx / NTOK, j = idx % NTOK;
    int ri = i / WIN, ci = i % WIN;
    int rj = j / WIN, cj = j % WIN;
    int t = (ri - rj + WIN - 1) * (2 * WIN - 1) + (ci - cj + WIN - 1);
#pragma unroll
    for (int h = 0; h < HEADS; h++)
        g_bias[h * (NTOK * NTOK) + idx] = table[t * HEADS + h];
}

// ---------------------------------------------------------------------------
// Kernel: fp32 SGEMM  C[M,N] = A[M,K] @ B[K,N] + bias[N]
// 128x128 block tile, 8-deep K tile, 8x8 per thread. M%128==0, N%128==0, K%8==0.
// ---------------------------------------------------------------------------
__global__ __launch_bounds__(256) void sgemm_kernel(
    const float* __restrict__ A, const float* __restrict__ B,
    const float* __restrict__ bias, float* __restrict__ C,
    int M, int N, int K)
{
    __shared__ float As[8][128];   // [k][m] (transposed)
    __shared__ float Bs[8][128];   // [k][n]

    const int tid = threadIdx.x;
    const int row0 = blockIdx.y * 128;
    const int col0 = blockIdx.x * 128;

    // global load mapping
    const int arow = tid >> 1;           // 0..127
    const int acol = (tid & 1) * 4;      // 0 or 4
    const int brow = tid >> 5;           // 0..7
    const int bcol = (tid & 31) * 4;     // 0..124

    const float* Aptr = A + (size_t)(row0 + arow) * K + acol;
    const float* Bptr = B + (size_t)brow * N + col0 + bcol;

    const int tx = tid & 15;
    const int ty = tid >> 4;

    float acc[8][8];
#pragma unroll
    for (int i = 0; i < 8; i++)
#pragma unroll
        for (int j = 0; j < 8; j++) acc[i][j] = 0.0f;

    for (int k0 = 0; k0 < K; k0 += 8) {
        float4 av = *(const float4*)(Aptr + k0);
        float4 bv = *(const float4*)(Bptr + (size_t)k0 * N);
        __syncthreads();
        As[acol + 0][arow] = av.x;
        As[acol + 1][arow] = av.y;
        As[acol + 2][arow] = av.z;
        As[acol + 3][arow] = av.w;
        *(float4*)&Bs[brow][bcol] = bv;
        __syncthreads();
#pragma unroll
        for (int kk = 0; kk < 8; kk++) {
            float a[8], b[8];
            *(float4*)(a)     = *(const float4*)&As[kk][ty * 8];
            *(float4*)(a + 4) = *(const float4*)&As[kk][ty * 8 + 4];
            *(float4*)(b)     = *(const float4*)&Bs[kk][tx * 8];
            *(float4*)(b + 4) = *(const float4*)&Bs[kk][tx * 8 + 4];
#pragma unroll
            for (int i = 0; i < 8; i++)
#pragma unroll
                for (int j = 0; j < 8; j++)
                    acc[i][j] = fmaf(a[i], b[j], acc[i][j]);
        }
    }

    // epilogue with bias
    float bb[8];
#pragma unroll
    for (int j = 0; j < 8; j++) bb[j] = bias[col0 + tx * 8 + j];

#pragma unroll
    for (int i = 0; i < 8; i++) {
        float* Crow = C + (size_t)(row0 + ty * 8 + i) * N + col0 + tx * 8;
        float4 v0, v1;
        v0.x = acc[i][0] + bb[0]; v0.y = acc[i][1] + bb[1];
        v0.z = acc[i][2] + bb[2]; v0.w = acc[i][3] + bb[3];
        v1.x = acc[i][4] + bb[4]; v1.y = acc[i][5] + bb[5];
        v1.z = acc[i][6] + bb[6]; v1.w = acc[i][7] + bb[7];
        *(float4*)(Crow)     = v0;
        *(float4*)(Crow + 4) = v1;
    }
}

// ---------------------------------------------------------------------------
// Kernel: per-(b,h) window attention.
// smem: S[196][197] (padded) + KV[196][64]  = 204,624 B (opt-in dynamic smem)
// Thread i (<196) owns row i: q in regs, S row to smem, softmax, P@V to regs.
// ---------------------------------------------------------------------------
#define S_LD   197
#define SMEM_ATTN ((NTOK * S_LD + NTOK * HDIM) * (int)sizeof(float))

__global__ __launch_bounds__(256) void attn_kernel() {
    extern __shared__ float smem[];
    float* S  = smem;                  // 196 * 197
    float* KV = smem + NTOK * S_LD;    // 196 * 64

    const int h = blockIdx.x;
    const int b = blockIdx.y;
    const int tid = threadIdx.x;

    const size_t rowbase = (size_t)b * NTOK;

    // ---- load K tile (cols 512..1023 of qkv) ----
    for (int t = tid; t < NTOK * (HDIM / 4); t += blockDim.x) {
        int r = t >> 4, d4 = (t & 15);
        float4 v = *(const float4*)(g_qkv + (rowbase + r) * (3 * DIM)
                                    + DIM + h * HDIM + d4 * 4);
        *(float4*)&KV[r * HDIM + d4 * 4] = v;
    }
    __syncthreads();

    const int i = tid;
    float rsum = 0.0f;

    if (i < NTOK) {
        // q row into registers
        float4 q4[16];
        const float* qptr = g_qkv + (rowbase + i) * (3 * DIM) + h * HDIM;
#pragma unroll
        for (int t = 0; t < 16; t++) q4[t] = *(const float4*)(qptr + t * 4);

        const float* biasrow = g_bias + h * (NTOK * NTOK) + i * NTOK;

        float maxv = -1e30f;
        for (int j = 0; j < NTOK; j++) {
            float s0 = 0.f, s1 = 0.f, s2 = 0.f, s3 = 0.f;
            const float4* kj = (const float4*)&KV[j * HDIM];
#pragma unroll
            for (int d4 = 0; d4 < 16; d4++) {
                float4 kv = kj[d4];
                s0 = fmaf(q4[d4].x, kv.x, s0);
                s1 = fmaf(q4[d4].y, kv.y, s1);
                s2 = fmaf(q4[d4].z, kv.z, s2);
                s3 = fmaf(q4[d4].w, kv.w, s3);
            }
            float s = (s0 + s1 + s2 + s3) * SCALE_F + biasrow[j];
            S[i * S_LD + j] = s;
            maxv = fmaxf(maxv, s);
        }
        // softmax (polynomial exp, MUFU-free)
        float sum = 0.0f;
        for (int j = 0; j < NTOK; j++) {
            float p = fast_exp(S[i * S_LD + j] - maxv);
            S[i * S_LD + j] = p;
            sum += p;
        }
        rsum = 1.0f / sum;
    }
    __syncthreads();

    // ---- overwrite KV with V tile (cols 1024..1535) ----
    for (int t = tid; t < NTOK * (HDIM / 4); t += blockDim.x) {
        int r = t >> 4, d4 = (t & 15);
        float4 v = *(const float4*)(g_qkv + (rowbase + r) * (3 * DIM)
                                    + 2 * DIM + h * HDIM + d4 * 4);
        *(float4*)&KV[r * HDIM + d4 * 4] = v;
    }
    __syncthreads();

    if (i < NTOK) {
        float4 acc[16];
#pragma unroll
        for (int t = 0; t < 16; t++) acc[t] = make_float4(0.f, 0.f, 0.f, 0.f);

        for (int j = 0; j < NTOK; j++) {
            float p = S[i * S_LD + j];
            const float4* vj = (const float4*)&KV[j * HDIM];
#pragma unroll
            for (int d4 = 0; d4 < 16; d4++) {
                float4 vv = vj[d4];
                acc[d4].x = fmaf(p, vv.x, acc[d4].x);
                acc[d4].y = fmaf(p, vv.y, acc[d4].y);
                acc[d4].z = fmaf(p, vv.z, acc[d4].z);
                acc[d4].w = fmaf(p, vv.w, acc[d4].w);
            }
        }
        float* optr = g_attn + (rowbase + i) * DIM + h * HDIM;
#pragma unroll
        for (int d4 = 0; d4 < 16; d4++) {
            float4 o;
            o.x = acc[d4].x * rsum; o.y = acc[d4].y * rsum;
            o.z = acc[d4].z * rsum; o.w = acc[d4].w * rsum;
            *(float4*)(optr + d4 * 4) = o;
        }
    }
}

// ---------------------------------------------------------------------------
// Launch
// ---------------------------------------------------------------------------
extern "C" void kernel_launch(void* const* d_in, const int* in_sizes, int n_in,
                              void* d_out, int out_size)
{
    const float* x          = (const float*)d_in[0];
    const float* w_qkv      = (const float*)d_in[1];
    const float* b_qkv      = (const float*)d_in[2];
    const float* w_proj     = (const float*)d_in[3];
    const float* b_proj     = (const float*)d_in[4];
    const float* bias_table = (const float*)d_in[5];
    float* out              = (float*)d_out;

    float* qkv;  cudaGetSymbolAddress((void**)&qkv,  g_qkv);
    float* attn; cudaGetSymbolAddress((void**)&attn, g_attn);

    static bool configured = false;
    if (!configured) {
        cudaFuncSetAttribute(attn_kernel,
                             cudaFuncAttributeMaxDynamicSharedMemorySize,
                             SMEM_ATTN);
        configured = true;
    }

    // 1) relative-position bias gather
    bias_gather_kernel<<<(NTOK * NTOK + 255) / 256, 256>>>(bias_table);

    // 2) QKV GEMM: [100352,512] @ [512,1536] + b
    {
        dim3 grid(3 * DIM / 128, MROWS / 128);
        sgemm_kernel<<<grid, 256>>>(x, w_qkv, b_qkv, qkv,
                                    MROWS, 3 * DIM, DIM);
    }

    // 3) window attention per (h, b)
    {
        dim3 grid(HEADS, BATCH);
        attn_kernel<<<grid, 256, SMEM_ATTN>>>();
    }

    // 4) output projection: [100352,512] @ [512,512] + b
    {
        dim3 grid(DIM / 128, MROWS / 128);
        sgemm_kernel<<<grid, 256>>>(attn, w_proj, b_proj, out,
                                    MROWS, DIM, DIM);
    }
}

// round 2
// speedup vs baseline: 1.6730x; 1.6730x over previous
#include <cuda_runtime.h>
#include <cuda_bf16.h>
#include <cstdint>

// ---------------------------------------------------------------------------
// Problem constants
// ---------------------------------------------------------------------------
#define BATCH   512
#define NTOK    196          // 14*14 window
#define DIM     512
#define HEADS   8
#define HDIM    64           // DIM / HEADS
#define MROWS   (BATCH * NTOK)       // 100352
#define WIN     14
#define SCALE_F 0.125f       // 64^-0.5

// ---------------------------------------------------------------------------
// Scratch (device globals: allocation-free contract)
// ---------------------------------------------------------------------------
__device__ float g_qkv [(size_t)MROWS * 3 * DIM];   // ~616 MB
__device__ float g_attn[(size_t)MROWS * DIM];       // ~205 MB
__device__ float g_bias[HEADS * NTOK * NTOK];       // ~1.2 MB

// ---------------------------------------------------------------------------
// Fast exp (MUFU-free): degree-6 exp2 polynomial
// ---------------------------------------------------------------------------
__device__ __forceinline__ float fast_exp(float x) {
    float t = x * 1.4426950408889634f;
    t = fmaxf(t, -126.0f);
    float fi = floorf(t);
    float f  = t - fi;
    float p = 1.5413220e-4f;
    p = fmaf(p, f, 1.3333558e-3f);
    p = fmaf(p, f, 9.6181291e-3f);
    p = fmaf(p, f, 5.5504109e-2f);
    p = fmaf(p, f, 2.4022651e-1f);
    p = fmaf(p, f, 6.9314718e-1f);
    p = fmaf(p, f, 1.0f);
    int ei = (int)fi;
    float sc = __int_as_float((unsigned)(ei + 127) << 23);
    return p * sc;
}

// ---------------------------------------------------------------------------
// Bias gather
// ---------------------------------------------------------------------------
__global__ void bias_gather_kernel(const float* __restrict__ table) {
    int idx = blockIdx.x * blockDim.x + threadIdx.x;
    if (idx >= NTOK * NTOK) return;
    int i = idx / NTOK, j = idx % NTOK;
    int ri = i / WIN, ci = i % WIN;
    int rj = j / WIN, cj = j % WIN;
    int t = (ri - rj + WIN - 1) * (2 * WIN - 1) + (ci - cj + WIN - 1);
#pragma unroll
    for (int h = 0; h < HEADS; h++)
        g_bias[h * (NTOK * NTOK) + idx] = table[t * HEADS + h];
}

// ---------------------------------------------------------------------------
// Tensor-core GEMM, fp32 in/out, internal bf16 hi/lo split (3-MMA emulation).
// C[M,N] = A[M,K] @ B[K,N] + bias[N].  Requires M%128==0, N%128==0, K%32==0.
// 128x128 block tile, 8 warps (each 64x32), K-tile 32.
// ---------------------------------------------------------------------------
#define KSA 40    // A smem k-stride (elems): 80B, 16B-aligned rows, conflict-free
#define KSB 136   // B smem n-stride (elems): 272B ≡ 4 words mod 32, conflict-free

__device__ __forceinline__ void mma_bf16(
    float& c0, float& c1, float& c2, float& c3,
    uint32_t a0, uint32_t a1, uint32_t a2, uint32_t a3,
    uint32_t b0, uint32_t b1)
{
    asm volatile(
        "mma.sync.aligned.m16n8k16.row.col.f32.bf16.bf16.f32 "
        "{%0,%1,%2,%3}, {%4,%5,%6,%7}, {%8,%9}, {%0,%1,%2,%3};\n"
        : "+f"(c0), "+f"(c1), "+f"(c2), "+f"(c3)
        : "r"(a0), "r"(a1), "r"(a2), "r"(a3), "r"(b0), "r"(b1));
}

#define LDSM_X4(r0,r1,r2,r3,addr) \
    asm volatile("ldmatrix.sync.aligned.m8n8.x4.shared.b16 {%0,%1,%2,%3}, [%4];" \
        : "=r"(r0),"=r"(r1),"=r"(r2),"=r"(r3) : "r"(addr))

#define LDSM_X4_T(r0,r1,r2,r3,addr) \
    asm volatile("ldmatrix.sync.aligned.m8n8.x4.trans.shared.b16 {%0,%1,%2,%3}, [%4];" \
        : "=r"(r0),"=r"(r1),"=r"(r2),"=r"(r3) : "r"(addr))

__device__ __forceinline__ void split_pack(float x0, float x1,
                                           uint32_t& hi, uint32_t& lo,
                                           bool first)
{
    __nv_bfloat16 h0 = __float2bfloat16(x0);
    __nv_bfloat16 h1 = __float2bfloat16(x1);
    __nv_bfloat16 l0 = __float2bfloat16(x0 - __bfloat162float(h0));
    __nv_bfloat16 l1 = __float2bfloat16(x1 - __bfloat162float(h1));
    uint32_t hw = ((uint32_t)*(uint16_t*)&h1 << 16) | *(uint16_t*)&h0;
    uint32_t lw = ((uint32_t)*(uint16_t*)&l1 << 16) | *(uint16_t*)&l0;
    if (first) { hi = hw; lo = lw; }
    else       { hi = hw; lo = lw; }
}

__global__ __launch_bounds__(256) void gemm_bf16x2_kernel(
    const float* __restrict__ A, const float* __restrict__ B,
    const float* __restrict__ bias, float* __restrict__ C,
    int M, int N, int K)
{
    __shared__ __align__(16) __nv_bfloat16 sAhi[128 * KSA];
    __shared__ __align__(16) __nv_bfloat16 sAlo[128 * KSA];
    __shared__ __align__(16) __nv_bfloat16 sBhi[32 * KSB];
    __shared__ __align__(16) __nv_bfloat16 sBlo[32 * KSB];

    const int tid  = threadIdx.x;
    const int warp = tid >> 5;
    const int lane = tid & 31;
    const int wm = warp & 1;           // 0..1 -> m offset 0/64
    const int wn = warp >> 1;          // 0..3 -> n offset 0/32/64/96
    const int row0 = blockIdx.y * 128;
    const int col0 = blockIdx.x * 128;

    // global-load mapping
    const int aRow = tid >> 3;          // 0..31 (x4 slabs of 32 rows)
    const int aK   = (tid & 7) * 4;     // 0..28
    const int bK   = tid >> 5;          // 0..7  (x4 slabs of 8 k-rows)
    const int bN   = (lane) * 4;        // 0..124

    const uint32_t uAhi = (uint32_t)__cvta_generic_to_shared(sAhi);
    const uint32_t uAlo = (uint32_t)__cvta_generic_to_shared(sAlo);
    const uint32_t uBhi = (uint32_t)__cvta_generic_to_shared(sBhi);
    const uint32_t uBlo = (uint32_t)__cvta_generic_to_shared(sBlo);

    // ldmatrix per-lane base offsets (in elements)
    const int aBase = (wm * 64 + (lane & 15)) * KSA + (lane >> 4) * 8;
    const int bBase = (((lane >> 3) & 1) * 8 + (lane & 7)) * KSB
                    + wn * 32 + (lane >> 4) * 8;

    float acc[4][4][4];
#pragma unroll
    for (int i = 0; i < 4; i++)
#pragma unroll
        for (int j = 0; j < 4; j++)
#pragma unroll
            for (int r = 0; r < 4; r++) acc[i][j][r] = 0.0f;

    // prefetch first K-tile into registers
    float4 ra[4], rb[4];
#pragma unroll
    for (int s = 0; s < 4; s++) {
        ra[s] = *(const float4*)(A + (size_t)(row0 + aRow + s * 32) * K + aK);
        rb[s] = *(const float4*)(B + (size_t)(bK + s * 8) * N + col0 + bN);
    }

    const int nkt = K / 32;
    for (int kt = 0; kt < nkt; kt++) {
        __syncthreads();   // previous compute done reading smem
        // stage registers -> smem (bf16 hi/lo)
#pragma unroll
        for (int s = 0; s < 4; s++) {
            {
                float4 v = ra[s];
                uint32_t h0, l0, h1, l1;
                split_pack(v.x, v.y, h0, l0, true);
                split_pack(v.z, v.w, h1, l1, true);
                int off = (aRow + s * 32) * KSA + aK;
                *(uint2*)&sAhi[off] = make_uint2(h0, h1);
                *(uint2*)&sAlo[off] = make_uint2(l0, l1);
            }
            {
                float4 v = rb[s];
                uint32_t h0, l0, h1, l1;
                split_pack(v.x, v.y, h0, l0, true);
                split_pack(v.z, v.w, h1, l1, true);
                int off = (bK + s * 8) * KSB + bN;
                *(uint2*)&sBhi[off] = make_uint2(h0, h1);
                *(uint2*)&sBlo[off] = make_uint2(l0, l1);
            }
        }
        __syncthreads();

        // prefetch next K-tile (latency hidden under MMA work below)
        if (kt + 1 < nkt) {
            const int k0 = (kt + 1) * 32;
#pragma unroll
            for (int s = 0; s < 4; s++) {
                ra[s] = *(const float4*)(A + (size_t)(row0 + aRow + s * 32) * K + k0 + aK);
                rb[s] = *(const float4*)(B + (size_t)(k0 + bK + s * 8) * N + col0 + bN);
            }
        }

        // two k-steps of 16
#pragma unroll
        for (int kk = 0; kk < 32; kk += 16) {
            uint32_t bh[4][2], bl[4][2];
#pragma unroll
            for (int p = 0; p < 2; p++) {
                uint32_t r0, r1, r2, r3;
                uint32_t addr = uBhi + 2 * (bBase + kk * KSB + p * 16);
                LDSM_X4_T(r0, r1, r2, r3, addr);
                bh[2*p][0] = r0; bh[2*p][1] = r1; bh[2*p+1][0] = r2; bh[2*p+1][1] = r3;
                addr = uBlo + 2 * (bBase + kk * KSB + p * 16);
                LDSM_X4_T(r0, r1, r2, r3, addr);
                bl[2*p][0] = r0; bl[2*p][1] = r1; bl[2*p+1][0] = r2; bl[2*p+1][1] = r3;
            }
#pragma unroll
            for (int mt = 0; mt < 4; mt++) {
                uint32_t ah0, ah1, ah2, ah3, al0, al1, al2, al3;
                uint32_t addr = uAhi + 2 * (aBase + mt * 16 * KSA + kk);
                LDSM_X4(ah0, ah1, ah2, ah3, addr);
                addr = uAlo + 2 * (aBase + mt * 16 * KSA + kk);
                LDSM_X4(al0, al1, al2, al3, addr);
#pragma unroll
                for (int nt = 0; nt < 4; nt++) {
                    mma_bf16(acc[mt][nt][0], acc[mt][nt][1], acc[mt][nt][2], acc[mt][nt][3],
                             ah0, ah1, ah2, ah3, bh[nt][0], bh[nt][1]);
                    mma_bf16(acc[mt][nt][0], acc[mt][nt][1], acc[mt][nt][2], acc[mt][nt][3],
                             ah0, ah1, ah2, ah3, bl[nt][0], bl[nt][1]);
                    mma_bf16(acc[mt][nt][0], acc[mt][nt][1], acc[mt][nt][2], acc[mt][nt][3],
                             al0, al1, al2, al3, bh[nt][0], bh[nt][1]);
                }
            }
        }
    }

    // epilogue: + bias, fp32 store
#pragma unroll
    for (int mt = 0; mt < 4; mt++) {
        const int r0 = row0 + wm * 64 + mt * 16 + (lane >> 2);
#pragma unroll
        for (int nt = 0; nt < 4; nt++) {
            const int c = col0 + wn * 32 + nt * 8 + (lane & 3) * 2;
            float b0 = __ldg(bias + c), b1 = __ldg(bias + c + 1);
            float2 v0 = make_float2(acc[mt][nt][0] + b0, acc[mt][nt][1] + b1);
            float2 v1 = make_float2(acc[mt][nt][2] + b0, acc[mt][nt][3] + b1);
            *(float2*)(C + (size_t)r0 * N + c)       = v0;
            *(float2*)(C + (size_t)(r0 + 8) * N + c) = v1;
        }
    }
}

// ---------------------------------------------------------------------------
// Per-(b,h) window attention (unchanged from R1 baseline)
// ---------------------------------------------------------------------------
#define S_LD   197
#define SMEM_ATTN ((NTOK * S_LD + NTOK * HDIM) * (int)sizeof(float))

__global__ __launch_bounds__(256) void attn_kernel() {
    extern __shared__ float smem[];
    float* S  = smem;
    float* KV = smem + NTOK * S_LD;

    const int h = blockIdx.x;
    const int b = blockIdx.y;
    const int tid = threadIdx.x;
    const size_t rowbase = (size_t)b * NTOK;

    for (int t = tid; t < NTOK * (HDIM / 4); t += blockDim.x) {
        int r = t >> 4, d4 = (t & 15);
        float4 v = *(const float4*)(g_qkv + (rowbase + r) * (3 * DIM)
                                    + DIM + h * HDIM + d4 * 4);
        *(float4*)&KV[r * HDIM + d4 * 4] = v;
    }
    __syncthreads();

    const int i = tid;
    float rsum = 0.0f;

    if (i < NTOK) {
        float4 q4[16];
        const float* qptr = g_qkv + (rowbase + i) * (3 * DIM) + h * HDIM;
#pragma unroll
        for (int t = 0; t < 16; t++) q4[t] = *(const float4*)(qptr + t * 4);

        const float* biasrow = g_bias + h * (NTOK * NTOK) + i * NTOK;

        float maxv = -1e30f;
        for (int j = 0; j < NTOK; j++) {
            float s0 = 0.f, s1 = 0.f, s2 = 0.f, s3 = 0.f;
            const float4* kj = (const float4*)&KV[j * HDIM];
#pragma unroll
            for (int d4 = 0; d4 < 16; d4++) {
                float4 kv = kj[d4];
                s0 = fmaf(q4[d4].x, kv.x, s0);
                s1 = fmaf(q4[d4].y, kv.y, s1);
                s2 = fmaf(q4[d4].z, kv.z, s2);
                s3 = fmaf(q4[d4].w, kv.w, s3);
            }
            float s = (s0 + s1 + s2 + s3) * SCALE_F + biasrow[j];
            S[i * S_LD + j] = s;
            maxv = fmaxf(maxv, s);
        }
        float sum = 0.0f;
        for (int j = 0; j < NTOK; j++) {
            float p = fast_exp(S[i * S_LD + j] - maxv);
            S[i * S_LD + j] = p;
            sum += p;
        }
        rsum = 1.0f / sum;
    }
    __syncthreads();

    for (int t = tid; t < NTOK * (HDIM / 4); t += blockDim.x) {
        int r = t >> 4, d4 = (t & 15);
        float4 v = *(const float4*)(g_qkv + (rowbase + r) * (3 * DIM)
                                    + 2 * DIM + h * HDIM + d4 * 4);
        *(float4*)&KV[r * HDIM + d4 * 4] = v;
    }
    __syncthreads();

    if (i < NTOK) {
        float4 acc[16];
#pragma unroll
        for (int t = 0; t < 16; t++) acc[t] = make_float4(0.f, 0.f, 0.f, 0.f);

        for (int j = 0; j < NTOK; j++) {
            float p = S[i * S_LD + j];
            const float4* vj = (const float4*)&KV[j * HDIM];
#pragma unroll
            for (int d4 = 0; d4 < 16; d4++) {
                float4 vv = vj[d4];
                acc[d4].x = fmaf(p, vv.x, acc[d4].x);
                acc[d4].y = fmaf(p, vv.y, acc[d4].y);
                acc[d4].z = fmaf(p, vv.z, acc[d4].z);
                acc[d4].w = fmaf(p, vv.w, acc[d4].w);
            }
        }
        float* optr = g_attn + (rowbase + i) * DIM + h * HDIM;
#pragma unroll
        for (int d4 = 0; d4 < 16; d4++) {
            float4 o;
            o.x = acc[d4].x * rsum; o.y = acc[d4].y * rsum;
            o.z = acc[d4].z * rsum; o.w = acc[d4].w * rsum;
            *(float4*)(optr + d4 * 4) = o;
        }
    }
}

// ---------------------------------------------------------------------------
// Launch
// ---------------------------------------------------------------------------
extern "C" void kernel_launch(void* const* d_in, const int* in_sizes, int n_in,
                              void* d_out, int out_size)
{
    const float* x          = (const float*)d_in[0];
    const float* w_qkv      = (const float*)d_in[1];
    const float* b_qkv      = (const float*)d_in[2];
    const float* w_proj     = (const float*)d_in[3];
    const float* b_proj     = (const float*)d_in[4];
    const float* bias_table = (const float*)d_in[5];
    float* out              = (float*)d_out;

    float* qkv;  cudaGetSymbolAddress((void**)&qkv,  g_qkv);
    float* attn; cudaGetSymbolAddress((void**)&attn, g_attn);

    static bool configured = false;
    if (!configured) {
        cudaFuncSetAttribute(attn_kernel,
                             cudaFuncAttributeMaxDynamicSharedMemorySize,
                             SMEM_ATTN);
        configured = true;
    }

    // 1) relative-position bias gather
    bias_gather_kernel<<<(NTOK * NTOK + 255) / 256, 256>>>(bias_table);

    // 2) QKV GEMM: [100352,512] @ [512,1536] + b   (tensor cores, bf16x2)
    {
        dim3 grid(3 * DIM / 128, MROWS / 128);
        gemm_bf16x2_kernel<<<grid, 256>>>(x, w_qkv, b_qkv, qkv,
                                          MROWS, 3 * DIM, DIM);
    }

    // 3) window attention per (h, b)
    {
        dim3 grid(HEADS, BATCH);
        attn_kernel<<<grid, 256, SMEM_ATTN>>>();
    }

    // 4) output projection: [100352,512] @ [512,512] + b
    {
        dim3 grid(DIM / 128, MROWS / 128);
        gemm_bf16x2_kernel<<<grid, 256>>>(attn, w_proj, b_proj, out,
                                          MROWS, DIM, DIM);
    }
}